// round 13
// baseline (speedup 1.0000x reference)
#include <cuda_runtime.h>
#include <math.h>
#include <stdint.h>

#define CB 2
#define CT 2048
#define CD 1024
#define CH 16
#define CM (CB*CT)   // 4096

#define BM 128
#define BN 256
#define BK 32
#define NITER (CD/BK)   // 32
#define NSTG 2
#define A_STG_B 16384
#define B_STG_B 32768
#define STG_B (A_STG_B + B_STG_B)          // 49152
#define GEMM_SMEM (NSTG*STG_B)             // 98304
#define ATTN_SMEM (2*32768)                // 65536

// Scratch (device globals; all in fragment order)
__device__ float g_xp[CM*CD];        // x as A-frags
__device__ float g_wp[4][CD*CD];     // wq,wk,wv,wo as B-frags
__device__ float g_qp[CM*CD];        // Q A-frags per (bh,qb)
__device__ float g_kp[CM*CD];        // K B-frags per (bh,kb)
__device__ float g_vp[CM*CD];        // V B-frags per (bh,kb)
__device__ float g_catp[CM*CD];      // concat as A-frags

__device__ __forceinline__ float rna_tf32(float x) {
    uint32_t r;
    asm("cvt.rna.tf32.f32 %0, %1;" : "=r"(r) : "f"(x));
    return __uint_as_float(r);
}
__device__ __forceinline__ uint32_t smem_u32(const void* p) {
    uint32_t a;
    asm("{ .reg .u64 t; cvta.to.shared.u64 t, %1; cvt.u32.u64 %0, t; }" : "=r"(a) : "l"(p));
    return a;
}
__device__ __forceinline__ void cpasync16(uint32_t dst, const void* src) {
    asm volatile("cp.async.cg.shared.global [%0], [%1], 16;" :: "r"(dst), "l"(src));
}
#define CP_COMMIT() asm volatile("cp.async.commit_group;")
#define CP_WAIT(n)  asm volatile("cp.async.wait_group %0;" :: "n"(n))

__device__ __forceinline__ void mma8(float c[4], const uint32_t a[4],
                                     uint32_t b0, uint32_t b1) {
    asm volatile(
        "mma.sync.aligned.m16n8k8.row.col.f32.tf32.tf32.f32 "
        "{%0,%1,%2,%3}, {%4,%5,%6,%7}, {%8,%9}, {%0,%1,%2,%3};"
        : "+f"(c[0]), "+f"(c[1]), "+f"(c[2]), "+f"(c[3])
        : "r"(a[0]), "r"(a[1]), "r"(a[2]), "r"(a[3]), "r"(b0), "r"(b1));
}

// ---------------------------------------------------------------------------
// Prepass: fp32 -> tf32(rna) + permute into fragment order.
// ---------------------------------------------------------------------------
__global__ __launch_bounds__(256) void permA(const float* __restrict__ in,
                                             float* __restrict__ out) {
    int gid = blockIdx.x * 256 + threadIdx.x;
    int lane = gid & 31, frag = gid >> 5;
    int kf = frag & 127, mf = frag >> 7;
    int mi = lane >> 2, ki = lane & 3;
    const float* p = in + (size_t)(mf * 16 + mi) * CD + kf * 8 + ki;
    float4 v;
    v.x = rna_tf32(p[0]);
    v.y = rna_tf32(p[8 * CD]);
    v.z = rna_tf32(p[4]);
    v.w = rna_tf32(p[8 * CD + 4]);
    ((float4*)out)[gid] = v;
}
__global__ __launch_bounds__(256) void permB(const float* __restrict__ in,
                                             float* __restrict__ out) {
    int gid = blockIdx.x * 256 + threadIdx.x;
    int lane = gid & 31, frag = gid >> 5;
    int kf = frag & 127, nf = frag >> 7;
    int ni = lane >> 2, ki = lane & 3;
    const float* p = in + (size_t)(nf * 8 + ni) * CD + kf * 8 + ki;
    ((float2*)out)[gid] = make_float2(rna_tf32(p[0]), rna_tf32(p[4]));
}

// ---------------------------------------------------------------------------
// tf32 GEMM on pre-permuted fragments. cp.async 2-stage pipeline (96KB smem).
// BM=128, BN=256; 8 warps (2x4); warp tile 64x64 (acc[4][8][4]).
// mode 0: row-major fp32 out
// mode 1: Q=RoPE->Q-frags  mode 2: K=RoPE->K-frags  mode 3: V->V-frags
// ---------------------------------------------------------------------------
__global__ __launch_bounds__(256) void gemm_f(
    const float* __restrict__ A, const float* __restrict__ W,
    float* __restrict__ out, int mode)
{
    extern __shared__ float sm[];
    const uint32_t sbase = smem_u32(sm);
    const int tid = threadIdx.x;
    const int wid = tid >> 5, lane = tid & 31;
    const int wr = wid >> 2, wc = wid & 3;      // 2 x 4 warp grid
    const int m0 = blockIdx.y * BM, n0 = blockIdx.x * BN;

    auto issue = [&](int kt) {
        int st = kt % NSTG;
        uint32_t dA = sbase + st * STG_B;
        #pragma unroll
        for (int p = 0; p < 4; p++) {           // 1024 x 16B = 16KB
            int idx = tid + p * 256;
            int fm = idx >> 7, inner = idx & 127;
            const float* s = A + ((size_t)(m0 / 16 + fm) * (CD / 8) + kt * 4) * 128 + inner * 4;
            cpasync16(dA + idx * 16, s);
        }
        uint32_t dB = dA + A_STG_B;
        #pragma unroll
        for (int p = 0; p < 8; p++) {           // 2048 x 16B = 32KB
            int idx = tid + p * 256;
            int fn = idx >> 6, inner = idx & 63;
            const float* s = W + ((size_t)(n0 / 8 + fn) * (CD / 8) + kt * 4) * 64 + inner * 4;
            cpasync16(dB + idx * 16, s);
        }
    };

    issue(0); CP_COMMIT();
    issue(1); CP_COMMIT();

    float acc[4][8][4] = {};

    for (int kt = 0; kt < NITER; kt++) {
        const int st = kt % NSTG;
        const float* As = sm + st * (STG_B / 4);
        const float* Bs = As + (A_STG_B / 4);
        CP_WAIT(1);
        __syncthreads();
        #pragma unroll
        for (int fk = 0; fk < 4; fk++) {
            uint32_t a[4][4], b[8][2];
            #pragma unroll
            for (int am = 0; am < 4; am++) {
                uint4 t = *(const uint4*)&As[(((wr * 4 + am) * 4 + fk) * 32 + lane) * 4];
                a[am][0] = t.x; a[am][1] = t.y; a[am][2] = t.z; a[am][3] = t.w;
            }
            #pragma unroll
            for (int bn = 0; bn < 8; bn++) {
                uint2 t = *(const uint2*)&Bs[(((wc * 8 + bn) * 4 + fk) * 32 + lane) * 2];
                b[bn][0] = t.x; b[bn][1] = t.y;
            }
            #pragma unroll
            for (int am = 0; am < 4; am++)
                #pragma unroll
                for (int bn = 0; bn < 8; bn++)
                    mma8(acc[am][bn], a[am], b[bn][0], b[bn][1]);
        }
        __syncthreads();
        if (kt + NSTG < NITER) issue(kt + NSTG);
        CP_COMMIT();
    }

    // ---- epilogue
    const int qrow = lane >> 2, qcol = (lane & 3) * 2;
    #pragma unroll
    for (int am = 0; am < 4; am++) {
        #pragma unroll
        for (int half = 0; half < 2; half++) {
            int m = m0 + (wr * 4 + am) * 16 + qrow + half * 8;
            int b_ = m >> 11, t = m & (CT - 1);
            #pragma unroll
            for (int bn = 0; bn < 8; bn++) {
                int col = n0 + (wc * 8 + bn) * 8 + qcol;
                float v0 = acc[am][bn][half * 2 + 0];
                float v1 = acc[am][bn][half * 2 + 1];
                if (mode == 0) {
                    *(float2*)&out[(size_t)m * CD + col] = make_float2(v0, v1);
                } else {
                    int h = col >> 6, d0 = col & 63;
                    int bh = b_ * CH + h;
                    if (mode <= 2) {   // RoPE for Q and K
                        int pidx = d0 >> 1;
                        float inv = exp2f(-(float)pidx * (9.965784284662087f / 32.0f));
                        float sn, cs;
                        sincosf((float)t * inv, &sn, &cs);
                        float re = v0 * cs - v1 * sn;
                        float ro = v0 * sn + v1 * cs;
                        v0 = re; v1 = ro;
                    }
                    if (mode == 1) {           // Q A-frags per (bh,qb64)
                        int qb = t >> 6, tq = t & 63, mf = tq >> 4, mi = tq & 15;
                        int kf = d0 >> 3, ki = d0 & 7;
                        int ls = (mi & 7) * 4 + (ki & 3);
                        int slot = ((ki & 4) >> 1) | (mi >> 3);
                        float* p = out + ((size_t)((bh * 32 + qb) * 4 + mf) * 8 + kf) * 128
                                       + ls * 4 + slot;
                        p[0] = rna_tf32(v0); p[4] = rna_tf32(v1);
                    } else if (mode == 2) {    // K B-frags per (bh,kb64)
                        int kb = t >> 6, tk = t & 63, nf = tk >> 3, ni = tk & 7;
                        int kf = d0 >> 3, ki = d0 & 7;
                        int ls = ni * 4 + (ki & 3), slot = ki >> 2;
                        float* p = out + ((size_t)((bh * 32 + kb) * 8 + kf) * 8 + nf) * 64
                                       + ls * 2 + slot;
                        p[0] = rna_tf32(v0); p[2] = rna_tf32(v1);
                    } else {                   // V B-frags per (bh,kb64)
                        int kb = t >> 6, keyl = t & 63, kf = keyl >> 3, ki = keyl & 7;
                        int nf = d0 >> 3, ni = d0 & 7;
                        int ls = ni * 4 + (ki & 3), slot = ki >> 2;
                        float* p = out + ((size_t)((bh * 32 + kb) * 8 + kf) * 8 + nf) * 64
                                       + ls * 2 + slot;
                        p[0] = rna_tf32(v0); p[8] = rna_tf32(v1);
                    }
                }
            }
        }
    }
}

// ---------------------------------------------------------------------------
// Flash attention on pre-permuted fragments (known-good R8 version).
// Q A-frags gmem->regs directly; K/V tiles cp.async double-buffered.
// Softmax on accumulator layout; P C-layout -> A-frag via register shuffles.
// cat written as A-frags.
// ---------------------------------------------------------------------------
__global__ __launch_bounds__(128) void attn_f(
    const float* __restrict__ Qp, const float* __restrict__ Kp,
    const float* __restrict__ Vp, float* __restrict__ catp)
{
    extern __shared__ float sm[];
    const uint32_t sbase = smem_u32(sm);
    const int qb = blockIdx.x, bh = blockIdx.y;
    const int tid = threadIdx.x, wid = tid >> 5, lane = tid & 31;

    // Q A-frags straight to registers (warp wid owns mf=wid), scaled by 1/8
    uint32_t qa[8][4];
    {
        const float* qsrc = Qp + ((size_t)((bh * 32 + qb) * 4 + wid)) * 1024 + lane * 4;
        #pragma unroll
        for (int kf = 0; kf < 8; kf++) {
            float4 t = *(const float4*)(qsrc + kf * 128);
            qa[kf][0] = __float_as_uint(t.x * 0.125f);
            qa[kf][1] = __float_as_uint(t.y * 0.125f);
            qa[kf][2] = __float_as_uint(t.z * 0.125f);
            qa[kf][3] = __float_as_uint(t.w * 0.125f);
        }
    }

    auto issueKV = [&](int kb) {
        int st = kb & 1;
        uint32_t d = sbase + st * 32768;
        const float* srcK = Kp + ((size_t)(bh * 32 + kb)) * 4096;
        const float* srcV = Vp + ((size_t)(bh * 32 + kb)) * 4096;
        #pragma unroll
        for (int u = 0; u < 8; u++) {
            int idx = tid + u * 128;
            cpasync16(d + idx * 16, srcK + idx * 4);
            cpasync16(d + 16384 + idx * 16, srcV + idx * 4);
        }
    };

    issueKV(0); CP_COMMIT();

    float m_[2] = {-1e30f, -1e30f}, l_[2] = {0.0f, 0.0f};
    float O[8][4] = {};

    const int src0 = (lane & ~3) | ((lane & 3) >> 1);
    const int src2 = src0 | 2;
    const bool sel = lane & 1;
    const int row0 = wid * 16 + (lane >> 2);

    for (int kb = 0; kb <= qb; kb++) {
        if (kb < qb) issueKV(kb + 1);
        CP_COMMIT();
        CP_WAIT(1);
        __syncthreads();
        const float* Ks = sm + (kb & 1) * 8192;
        const float* Vs = Ks + 4096;

        // ---- S = Q K^T
        float S[8][4] = {};
        #pragma unroll
        for (int kf = 0; kf < 8; kf++) {
            #pragma unroll
            for (int nf = 0; nf < 8; nf++) {
                uint2 kfr = *(const uint2*)&Ks[((kf * 8 + nf) * 32 + lane) * 2];
                mma8(S[nf], qa[kf], kfr.x, kfr.y);
            }
        }

        if (kb == qb) {
            #pragma unroll
            for (int nf = 0; nf < 8; nf++)
                #pragma unroll
                for (int e = 0; e < 4; e++) {
                    int col = nf * 8 + 2 * (lane & 3) + (e & 1);
                    int row = row0 + ((e >> 1) << 3);
                    if (col > row) S[nf][e] = -1e30f;
                }
        }

        // ---- online softmax (quad-lane reductions)
        #pragma unroll
        for (int h = 0; h < 2; h++) {
            float mx = -1e30f;
            #pragma unroll
            for (int nf = 0; nf < 8; nf++)
                mx = fmaxf(mx, fmaxf(S[nf][2*h], S[nf][2*h + 1]));
            mx = fmaxf(mx, __shfl_xor_sync(0xffffffffu, mx, 1));
            mx = fmaxf(mx, __shfl_xor_sync(0xffffffffu, mx, 2));
            float mn = fmaxf(m_[h], mx);
            float sc = __expf(m_[h] - mn);
            float rs = 0.0f;
            #pragma unroll
            for (int nf = 0; nf < 8; nf++) {
                float p0 = rna_tf32(__expf(S[nf][2*h]     - mn));
                float p1 = rna_tf32(__expf(S[nf][2*h + 1] - mn));
                S[nf][2*h] = p0; S[nf][2*h + 1] = p1;
                rs += p0 + p1;
            }
            rs += __shfl_xor_sync(0xffffffffu, rs, 1);
            rs += __shfl_xor_sync(0xffffffffu, rs, 2);
            l_[h] = l_[h] * sc + rs;
            m_[h] = mn;
            #pragma unroll
            for (int nf = 0; nf < 8; nf++) { O[nf][2*h] *= sc; O[nf][2*h + 1] *= sc; }
        }

        // ---- O += P V (P -> A-frag via shfl)
        #pragma unroll
        for (int j = 0; j < 8; j++) {
            float t00 = __shfl_sync(0xffffffffu, S[j][0], src0);
            float t01 = __shfl_sync(0xffffffffu, S[j][1], src0);
            float t20 = __shfl_sync(0xffffffffu, S[j][0], src2);
            float t21 = __shfl_sync(0xffffffffu, S[j][1], src2);
            float t10 = __shfl_sync(0xffffffffu, S[j][2], src0);
            float t11 = __shfl_sync(0xffffffffu, S[j][3], src0);
            float t30 = __shfl_sync(0xffffffffu, S[j][2], src2);
            float t31 = __shfl_sync(0xffffffffu, S[j][3], src2);
            uint32_t pa[4];
            pa[0] = __float_as_uint(sel ? t01 : t00);
            pa[1] = __float_as_uint(sel ? t11 : t10);
            pa[2] = __float_as_uint(sel ? t21 : t20);
            pa[3] = __float_as_uint(sel ? t31 : t30);
            #pragma unroll
            for (int nf = 0; nf < 8; nf++) {
                uint2 vf = *(const uint2*)&Vs[((j * 8 + nf) * 32 + lane) * 2];
                mma8(O[nf], pa, vf.x, vf.y);
            }
        }
        __syncthreads();
    }

    // ---- epilogue: write cat as A-frags (feeds out-proj)
    const int b_ = bh >> 4, h = bh & 15;
    #pragma unroll
    for (int h2 = 0; h2 < 2; h2++) {
        int t = qb * 64 + wid * 16 + (lane >> 2) + h2 * 8;
        int m = b_ * CT + t;
        float inv = 1.0f / l_[h2];
        int mf = m >> 4, mi = m & 15;
        #pragma unroll
        for (int nf = 0; nf < 8; nf++) {
            int d = nf * 8 + 2 * (lane & 3);
            int kcol = h * 64 + d;
            int kf = kcol >> 3, ki = d & 7;
            int ls = (mi & 7) * 4 + (ki & 3);
            int slot = ((ki & 4) >> 1) | (mi >> 3);
            float* p = catp + ((size_t)(mf * (CD / 8) + kf) * 32 + ls) * 4 + slot;
            p[0] = rna_tf32(O[nf][2*h2]     * inv);
            p[4] = rna_tf32(O[nf][2*h2 + 1] * inv);
        }
    }
}

extern "C" void kernel_launch(void* const* d_in, const int* in_sizes, int n_in,
                              void* d_out, int out_size) {
    const float* x  = (const float*)d_in[0];
    const float* wq = (const float*)d_in[1];
    const float* wk = (const float*)d_in[2];
    const float* wv = (const float*)d_in[3];
    const float* wo = (const float*)d_in[4];
    float* out = (float*)d_out;

    float *xp, *wp, *qp, *kp, *vp, *catp;
    cudaGetSymbolAddress((void**)&xp,   g_xp);
    cudaGetSymbolAddress((void**)&wp,   g_wp);
    cudaGetSymbolAddress((void**)&qp,   g_qp);
    cudaGetSymbolAddress((void**)&kp,   g_kp);
    cudaGetSymbolAddress((void**)&vp,   g_vp);
    cudaGetSymbolAddress((void**)&catp, g_catp);

    cudaFuncSetAttribute(gemm_f, cudaFuncAttributeMaxDynamicSharedMemorySize, GEMM_SMEM);
    cudaFuncSetAttribute(attn_f, cudaFuncAttributeMaxDynamicSharedMemorySize, ATTN_SMEM);

    permA<<<(CM/16)*(CD/8)*32/256, 256>>>(x, xp);
    permB<<<(CD/8)*(CD/8)*32/256, 256>>>(wq, wp + 0*CD*CD);
    permB<<<(CD/8)*(CD/8)*32/256, 256>>>(wk, wp + 1*CD*CD);
    permB<<<(CD/8)*(CD/8)*32/256, 256>>>(wv, wp + 2*CD*CD);
    permB<<<(CD/8)*(CD/8)*32/256, 256>>>(wo, wp + 3*CD*CD);

    dim3 gg(CD / BN, CM / BM);   // (4, 32) = 128 blocks: single wave
    gemm_f<<<gg, 256, GEMM_SMEM>>>(xp, wp + 0*CD*CD, qp, 1);
    gemm_f<<<gg, 256, GEMM_SMEM>>>(xp, wp + 1*CD*CD, kp, 2);
    gemm_f<<<gg, 256, GEMM_SMEM>>>(xp, wp + 2*CD*CD, vp, 3);

    dim3 ga(CT / 64, CB * CH);   // (32, 32)
    attn_f<<<ga, 128, ATTN_SMEM>>>(qp, kp, vp, catp);

    gemm_f<<<gg, 256, GEMM_SMEM>>>(catp, wp + 3*CD*CD, out, 0);
}

// round 14
// speedup vs baseline: 1.1816x; 1.1816x over previous
#include <cuda_runtime.h>
#include <math.h>
#include <stdint.h>

#define CB 2
#define CT 2048
#define CD 1024
#define CH 16
#define CM (CB*CT)   // 4096

#define BM 128
#define BN 128
#define BK 32
#define NITER (CD/BK)   // 32
#define NSTG 3
#define A_STG_B 16384
#define B_STG_B 16384
#define STG_B (A_STG_B + B_STG_B)          // 32768
#define GEMM_SMEM (NSTG*STG_B)             // 98304
#define ATTN_SMEM (2*32768)                // 65536

// Scratch (device globals; all in fragment order)
__device__ float g_xp[CM*CD];        // x as A-frags
__device__ float g_wp[4][CD*CD];     // wq,wk,wv,wo as B-frags
__device__ float g_qp[CM*CD];        // Q A-frags per (bh,qb)
__device__ float g_kp[CM*CD];        // K B-frags per (bh,kb)
__device__ float g_vp[CM*CD];        // V B-frags per (bh,kb)
__device__ float g_catp[CM*CD];      // concat as A-frags

__device__ __forceinline__ float rna_tf32(float x) {
    uint32_t r;
    asm("cvt.rna.tf32.f32 %0, %1;" : "=r"(r) : "f"(x));
    return __uint_as_float(r);
}
__device__ __forceinline__ uint32_t smem_u32(const void* p) {
    uint32_t a;
    asm("{ .reg .u64 t; cvta.to.shared.u64 t, %1; cvt.u32.u64 %0, t; }" : "=r"(a) : "l"(p));
    return a;
}
__device__ __forceinline__ void cpasync16(uint32_t dst, const void* src) {
    asm volatile("cp.async.cg.shared.global [%0], [%1], 16;" :: "r"(dst), "l"(src));
}
#define CP_COMMIT() asm volatile("cp.async.commit_group;")
#define CP_WAIT(n)  asm volatile("cp.async.wait_group %0;" :: "n"(n))

__device__ __forceinline__ void mma8(float c[4], const uint32_t a[4],
                                     uint32_t b0, uint32_t b1) {
    asm volatile(
        "mma.sync.aligned.m16n8k8.row.col.f32.tf32.tf32.f32 "
        "{%0,%1,%2,%3}, {%4,%5,%6,%7}, {%8,%9}, {%0,%1,%2,%3};"
        : "+f"(c[0]), "+f"(c[1]), "+f"(c[2]), "+f"(c[3])
        : "r"(a[0]), "r"(a[1]), "r"(a[2]), "r"(a[3]), "r"(b0), "r"(b1));
}

// ---------------------------------------------------------------------------
// Prepass: fp32 -> tf32(rna) + permute into fragment order.
// ---------------------------------------------------------------------------
__global__ __launch_bounds__(256) void permA(const float* __restrict__ in,
                                             float* __restrict__ out) {
    int gid = blockIdx.x * 256 + threadIdx.x;
    int lane = gid & 31, frag = gid >> 5;
    int kf = frag & 127, mf = frag >> 7;
    int mi = lane >> 2, ki = lane & 3;
    const float* p = in + (size_t)(mf * 16 + mi) * CD + kf * 8 + ki;
    float4 v;
    v.x = rna_tf32(p[0]);
    v.y = rna_tf32(p[8 * CD]);
    v.z = rna_tf32(p[4]);
    v.w = rna_tf32(p[8 * CD + 4]);
    ((float4*)out)[gid] = v;
}
__global__ __launch_bounds__(256) void permB(const float* __restrict__ in,
                                             float* __restrict__ out) {
    int gid = blockIdx.x * 256 + threadIdx.x;
    int lane = gid & 31, frag = gid >> 5;
    int kf = frag & 127, nf = frag >> 7;
    int ni = lane >> 2, ki = lane & 3;
    const float* p = in + (size_t)(nf * 8 + ni) * CD + kf * 8 + ki;
    ((float2*)out)[gid] = make_float2(rna_tf32(p[0]), rna_tf32(p[4]));
}

// ---------------------------------------------------------------------------
// tf32 GEMM on pre-permuted fragments (exact R8 config: BN=128, NSTG=3,
// warp tile 64x32). cp.async 3-stage pipeline.
// mode 0: row-major fp32 out
// mode 1: Q=RoPE->Q-frags  mode 2: K=RoPE->K-frags  mode 3: V->V-frags
// ---------------------------------------------------------------------------
__global__ __launch_bounds__(256) void gemm_f(
    const float* __restrict__ A, const float* __restrict__ W,
    float* __restrict__ out, int mode)
{
    extern __shared__ float sm[];
    const uint32_t sbase = smem_u32(sm);
    const int tid = threadIdx.x;
    const int wid = tid >> 5, lane = tid & 31;
    const int wr = wid >> 2, wc = wid & 3;      // 2 x 4 warp grid
    const int m0 = blockIdx.y * BM, n0 = blockIdx.x * BN;

    auto issue = [&](int kt) {
        int st = kt % NSTG;
        uint32_t dA = sbase + st * STG_B;
        #pragma unroll
        for (int p = 0; p < 4; p++) {           // 1024 x 16B = 16KB
            int idx = tid + p * 256;
            int fm = idx >> 7, inner = idx & 127;
            const float* s = A + ((size_t)(m0 / 16 + fm) * (CD / 8) + kt * 4) * 128 + inner * 4;
            cpasync16(dA + idx * 16, s);
        }
        uint32_t dB = dA + A_STG_B;
        #pragma unroll
        for (int p = 0; p < 4; p++) {           // 1024 x 16B = 16KB
            int idx = tid + p * 256;
            int fn = idx >> 6, inner = idx & 63;
            const float* s = W + ((size_t)(n0 / 8 + fn) * (CD / 8) + kt * 4) * 64 + inner * 4;
            cpasync16(dB + idx * 16, s);
        }
        asm volatile("cp.async.commit_group;");
    };

    issue(0);
    issue(1);
    issue(2);

    float acc[4][4][4] = {};

    for (int kt = 0; kt < NITER; kt++) {
        const int st = kt % NSTG;
        const float* As = sm + st * (STG_B / 4);
        const float* Bs = As + (A_STG_B / 4);
        CP_WAIT(2);
        __syncthreads();
        #pragma unroll
        for (int fk = 0; fk < 4; fk++) {
            uint32_t a[4][4], b[4][2];
            #pragma unroll
            for (int am = 0; am < 4; am++) {
                uint4 t = *(const uint4*)&As[(((wr * 4 + am) * 4 + fk) * 32 + lane) * 4];
                a[am][0] = t.x; a[am][1] = t.y; a[am][2] = t.z; a[am][3] = t.w;
            }
            #pragma unroll
            for (int bn = 0; bn < 4; bn++) {
                uint2 t = *(const uint2*)&Bs[(((wc * 4 + bn) * 4 + fk) * 32 + lane) * 2];
                b[bn][0] = t.x; b[bn][1] = t.y;
            }
            #pragma unroll
            for (int am = 0; am < 4; am++)
                #pragma unroll
                for (int bn = 0; bn < 4; bn++)
                    mma8(acc[am][bn], a[am], b[bn][0], b[bn][1]);
        }
        __syncthreads();
        if (kt + NSTG < NITER) issue(kt + NSTG);
    }

    // ---- epilogue
    const int qrow = lane >> 2, qcol = (lane & 3) * 2;
    #pragma unroll
    for (int am = 0; am < 4; am++) {
        #pragma unroll
        for (int half = 0; half < 2; half++) {
            int m = m0 + (wr * 4 + am) * 16 + qrow + half * 8;
            int b_ = m >> 11, t = m & (CT - 1);
            #pragma unroll
            for (int bn = 0; bn < 4; bn++) {
                int col = n0 + (wc * 4 + bn) * 8 + qcol;
                float v0 = acc[am][bn][half * 2 + 0];
                float v1 = acc[am][bn][half * 2 + 1];
                if (mode == 0) {
                    *(float2*)&out[(size_t)m * CD + col] = make_float2(v0, v1);
                } else {
                    int h = col >> 6, d0 = col & 63;
                    int bh = b_ * CH + h;
                    if (mode <= 2) {   // RoPE for Q and K
                        int pidx = d0 >> 1;
                        float inv = exp2f(-(float)pidx * (9.965784284662087f / 32.0f));
                        float sn, cs;
                        sincosf((float)t * inv, &sn, &cs);
                        float re = v0 * cs - v1 * sn;
                        float ro = v0 * sn + v1 * cs;
                        v0 = re; v1 = ro;
                    }
                    if (mode == 1) {           // Q A-frags per (bh,qb64)
                        int qb = t >> 6, tq = t & 63, mf = tq >> 4, mi = tq & 15;
                        int kf = d0 >> 3, ki = d0 & 7;
                        int ls = (mi & 7) * 4 + (ki & 3);
                        int slot = ((ki & 4) >> 1) | (mi >> 3);
                        float* p = out + ((size_t)((bh * 32 + qb) * 4 + mf) * 8 + kf) * 128
                                       + ls * 4 + slot;
                        p[0] = rna_tf32(v0); p[4] = rna_tf32(v1);
                    } else if (mode == 2) {    // K B-frags per (bh,kb64)
                        int kb = t >> 6, tk = t & 63, nf = tk >> 3, ni = tk & 7;
                        int kf = d0 >> 3, ki = d0 & 7;
                        int ls = ni * 4 + (ki & 3), slot = ki >> 2;
                        float* p = out + ((size_t)((bh * 32 + kb) * 8 + kf) * 8 + nf) * 64
                                       + ls * 2 + slot;
                        p[0] = rna_tf32(v0); p[2] = rna_tf32(v1);
                    } else {                   // V B-frags per (bh,kb64)
                        int kb = t >> 6, keyl = t & 63, kf = keyl >> 3, ki = keyl & 7;
                        int nf = d0 >> 3, ni = d0 & 7;
                        int ls = ni * 4 + (ki & 3), slot = ki >> 2;
                        float* p = out + ((size_t)((bh * 32 + kb) * 8 + kf) * 8 + nf) * 64
                                       + ls * 2 + slot;
                        p[0] = rna_tf32(v0); p[8] = rna_tf32(v1);
                    }
                }
            }
        }
    }
}

// ---------------------------------------------------------------------------
// Flash attention, Br=128 via 8 warps (256 threads). Per-warp register
// footprint identical to the proven R8 kernel (warp owns 16 query rows).
// K/V tile loads halve vs Br=64. Fully-masked diagonal sub-tiles skipped
// (exact: skipped tile => sc=1, rs=0 in online softmax).
// ---------------------------------------------------------------------------
__global__ __launch_bounds__(256, 2) void attn_f(
    const float* __restrict__ Qp, const float* __restrict__ Kp,
    const float* __restrict__ Vp, float* __restrict__ catp)
{
    extern __shared__ float sm[];
    const uint32_t sbase = smem_u32(sm);
    const int qb2 = blockIdx.x, bh = blockIdx.y;   // 128-row query tile
    const int tid = threadIdx.x, wid = tid >> 5, lane = tid & 31;

    // Q A-frags -> regs (scaled 1/8). Warp wid owns rows [16*wid, 16*wid+16).
    uint32_t qa[8][4];
    {
        int mfg = (bh * 32 + qb2 * 2 + (wid >> 2)) * 4 + (wid & 3);
        const float* qsrc = Qp + (size_t)mfg * 1024 + lane * 4;
        #pragma unroll
        for (int kf = 0; kf < 8; kf++) {
            float4 t = *(const float4*)(qsrc + kf * 128);
            qa[kf][0] = __float_as_uint(t.x * 0.125f);
            qa[kf][1] = __float_as_uint(t.y * 0.125f);
            qa[kf][2] = __float_as_uint(t.z * 0.125f);
            qa[kf][3] = __float_as_uint(t.w * 0.125f);
        }
    }

    auto issueKV = [&](int kb) {
        int st = kb & 1;
        uint32_t d = sbase + st * 32768;
        const float* srcK = Kp + ((size_t)(bh * 32 + kb)) * 4096;
        const float* srcV = Vp + ((size_t)(bh * 32 + kb)) * 4096;
        #pragma unroll
        for (int u = 0; u < 4; u++) {
            int idx = tid + u * 256;
            cpasync16(d + idx * 16, srcK + idx * 4);
            cpasync16(d + 16384 + idx * 16, srcV + idx * 4);
        }
    };

    issueKV(0); CP_COMMIT();

    float m_[2] = {-1e30f, -1e30f}, l_[2] = {0.0f, 0.0f};
    float O[8][4] = {};

    const int src0 = (lane & ~3) | ((lane & 3) >> 1);
    const int src2 = src0 | 2;
    const bool sel = lane & 1;
    const int row0 = qb2 * 128 + wid * 16 + (lane >> 2);
    const int kblast = 2 * qb2 + 1;

    for (int kb = 0; kb <= kblast; kb++) {
        if (kb < kblast) issueKV(kb + 1);
        CP_COMMIT();
        CP_WAIT(1);
        __syncthreads();

        // warps 0-3 are entirely above the kblast tile's columns: skip (exact)
        bool active = !(kb == kblast && wid < 4);
        if (active) {
            const float* Ks = sm + (kb & 1) * 8192;
            const float* Vs = Ks + 4096;

            // ---- S = Q K^T
            float S[8][4] = {};
            #pragma unroll
            for (int kf = 0; kf < 8; kf++) {
                #pragma unroll
                for (int nf = 0; nf < 8; nf++) {
                    uint2 kfr = *(const uint2*)&Ks[((kf * 8 + nf) * 32 + lane) * 2];
                    mma8(S[nf], qa[kf], kfr.x, kfr.y);
                }
            }

            if (kb >= 2 * qb2) {   // diagonal super-tiles: causal mask
                #pragma unroll
                for (int nf = 0; nf < 8; nf++)
                    #pragma unroll
                    for (int e = 0; e < 4; e++) {
                        int col = kb * 64 + nf * 8 + 2 * (lane & 3) + (e & 1);
                        int row = row0 + ((e >> 1) << 3);
                        if (col > row) S[nf][e] = -1e30f;
                    }
            }

            // ---- online softmax (quad-lane reductions)
            #pragma unroll
            for (int h = 0; h < 2; h++) {
                float mx = -1e30f;
                #pragma unroll
                for (int nf = 0; nf < 8; nf++)
                    mx = fmaxf(mx, fmaxf(S[nf][2*h], S[nf][2*h + 1]));
                mx = fmaxf(mx, __shfl_xor_sync(0xffffffffu, mx, 1));
                mx = fmaxf(mx, __shfl_xor_sync(0xffffffffu, mx, 2));
                float mn = fmaxf(m_[h], mx);
                float sc = __expf(m_[h] - mn);
                float rs = 0.0f;
                #pragma unroll
                for (int nf = 0; nf < 8; nf++) {
                    float p0 = rna_tf32(__expf(S[nf][2*h]     - mn));
                    float p1 = rna_tf32(__expf(S[nf][2*h + 1] - mn));
                    S[nf][2*h] = p0; S[nf][2*h + 1] = p1;
                    rs += p0 + p1;
                }
                rs += __shfl_xor_sync(0xffffffffu, rs, 1);
                rs += __shfl_xor_sync(0xffffffffu, rs, 2);
                l_[h] = l_[h] * sc + rs;
                m_[h] = mn;
                #pragma unroll
                for (int nf = 0; nf < 8; nf++) { O[nf][2*h] *= sc; O[nf][2*h + 1] *= sc; }
            }

            // ---- O += P V (P -> A-frag via shfl)
            #pragma unroll
            for (int j = 0; j < 8; j++) {
                float t00 = __shfl_sync(0xffffffffu, S[j][0], src0);
                float t01 = __shfl_sync(0xffffffffu, S[j][1], src0);
                float t20 = __shfl_sync(0xffffffffu, S[j][0], src2);
                float t21 = __shfl_sync(0xffffffffu, S[j][1], src2);
                float t10 = __shfl_sync(0xffffffffu, S[j][2], src0);
                float t11 = __shfl_sync(0xffffffffu, S[j][3], src0);
                float t30 = __shfl_sync(0xffffffffu, S[j][2], src2);
                float t31 = __shfl_sync(0xffffffffu, S[j][3], src2);
                uint32_t pa[4];
                pa[0] = __float_as_uint(sel ? t01 : t00);
                pa[1] = __float_as_uint(sel ? t11 : t10);
                pa[2] = __float_as_uint(sel ? t21 : t20);
                pa[3] = __float_as_uint(sel ? t31 : t30);
                #pragma unroll
                for (int nf = 0; nf < 8; nf++) {
                    uint2 vf = *(const uint2*)&Vs[((j * 8 + nf) * 32 + lane) * 2];
                    mma8(O[nf], pa, vf.x, vf.y);
                }
            }
        }
        __syncthreads();
    }

    // ---- epilogue: write cat as A-frags (feeds out-proj)
    const int b_ = bh >> 4, h = bh & 15;
    #pragma unroll
    for (int h2 = 0; h2 < 2; h2++) {
        int t = qb2 * 128 + wid * 16 + (lane >> 2) + h2 * 8;
        int m = b_ * CT + t;
        float inv = 1.0f / l_[h2];
        int mf = m >> 4, mi = m & 15;
        #pragma unroll
        for (int nf = 0; nf < 8; nf++) {
            int d = nf * 8 + 2 * (lane & 3);
            int kcol = h * 64 + d;
            int kf = kcol >> 3, ki = d & 7;
            int ls = (mi & 7) * 4 + (ki & 3);
            int slot = ((ki & 4) >> 1) | (mi >> 3);
            float* p = catp + ((size_t)(mf * (CD / 8) + kf) * 32 + ls) * 4 + slot;
            p[0] = rna_tf32(O[nf][2*h2]     * inv);
            p[4] = rna_tf32(O[nf][2*h2 + 1] * inv);
        }
    }
}

extern "C" void kernel_launch(void* const* d_in, const int* in_sizes, int n_in,
                              void* d_out, int out_size) {
    const float* x  = (const float*)d_in[0];
    const float* wq = (const float*)d_in[1];
    const float* wk = (const float*)d_in[2];
    const float* wv = (const float*)d_in[3];
    const float* wo = (const float*)d_in[4];
    float* out = (float*)d_out;

    float *xp, *wp, *qp, *kp, *vp, *catp;
    cudaGetSymbolAddress((void**)&xp,   g_xp);
    cudaGetSymbolAddress((void**)&wp,   g_wp);
    cudaGetSymbolAddress((void**)&qp,   g_qp);
    cudaGetSymbolAddress((void**)&kp,   g_kp);
    cudaGetSymbolAddress((void**)&vp,   g_vp);
    cudaGetSymbolAddress((void**)&catp, g_catp);

    cudaFuncSetAttribute(gemm_f, cudaFuncAttributeMaxDynamicSharedMemorySize, GEMM_SMEM);
    cudaFuncSetAttribute(attn_f, cudaFuncAttributeMaxDynamicSharedMemorySize, ATTN_SMEM);

    permA<<<(CM/16)*(CD/8)*32/256, 256>>>(x, xp);
    permB<<<(CD/8)*(CD/8)*32/256, 256>>>(wq, wp + 0*CD*CD);
    permB<<<(CD/8)*(CD/8)*32/256, 256>>>(wk, wp + 1*CD*CD);
    permB<<<(CD/8)*(CD/8)*32/256, 256>>>(wv, wp + 2*CD*CD);
    permB<<<(CD/8)*(CD/8)*32/256, 256>>>(wo, wp + 3*CD*CD);

    dim3 gg(CD / BN, CM / BM);   // (8, 32)
    gemm_f<<<gg, 256, GEMM_SMEM>>>(xp, wp + 0*CD*CD, qp, 1);
    gemm_f<<<gg, 256, GEMM_SMEM>>>(xp, wp + 1*CD*CD, kp, 2);
    gemm_f<<<gg, 256, GEMM_SMEM>>>(xp, wp + 2*CD*CD, vp, 3);

    dim3 ga(CT / 128, CB * CH);  // (16, 32)
    attn_f<<<ga, 256, ATTN_SMEM>>>(qp, kp, vp, catp);

    gemm_f<<<gg, 256, GEMM_SMEM>>>(catp, wp + 3*CD*CD, out, 0);
}

// round 15
// speedup vs baseline: 1.2237x; 1.0356x over previous
#include <cuda_runtime.h>
#include <math.h>
#include <stdint.h>

#define CB 2
#define CT 2048
#define CD 1024
#define CH 16
#define CM (CB*CT)   // 4096

#define BM 128
#define BN 128
#define BK 32
#define NITER (CD/BK)   // 32
#define NSTG 3
#define A_STG_B 16384
#define B_STG_B 16384
#define STG_B (A_STG_B + B_STG_B)          // 32768
#define GEMM_SMEM (NSTG*STG_B)             // 98304
#define ATTN_SMEM (2*32768)                // 65536

// Scratch (device globals; all in fragment order)
__device__ float g_xp[CM*CD];        // x as A-frags
__device__ float g_wp[4][CD*CD];     // wq,wk,wv,wo as B-frags
__device__ float g_qp[CM*CD];        // Q A-frags per (bh,qb)
__device__ float g_kp[CM*CD];        // K B-frags per (bh,kb)
__device__ float g_vp[CM*CD];        // V B-frags per (bh,kb)
__device__ float g_catp[CM*CD];      // concat as A-frags

__device__ __forceinline__ float rna_tf32(float x) {
    uint32_t r;
    asm("cvt.rna.tf32.f32 %0, %1;" : "=r"(r) : "f"(x));
    return __uint_as_float(r);
}
__device__ __forceinline__ uint32_t smem_u32(const void* p) {
    uint32_t a;
    asm("{ .reg .u64 t; cvta.to.shared.u64 t, %1; cvt.u32.u64 %0, t; }" : "=r"(a) : "l"(p));
    return a;
}
__device__ __forceinline__ void cpasync16(uint32_t dst, const void* src) {
    asm volatile("cp.async.cg.shared.global [%0], [%1], 16;" :: "r"(dst), "l"(src));
}
#define CP_COMMIT() asm volatile("cp.async.commit_group;")
#define CP_WAIT(n)  asm volatile("cp.async.wait_group %0;" :: "n"(n))

__device__ __forceinline__ void mma8(float c[4], const uint32_t a[4],
                                     uint32_t b0, uint32_t b1) {
    asm volatile(
        "mma.sync.aligned.m16n8k8.row.col.f32.tf32.tf32.f32 "
        "{%0,%1,%2,%3}, {%4,%5,%6,%7}, {%8,%9}, {%0,%1,%2,%3};"
        : "+f"(c[0]), "+f"(c[1]), "+f"(c[2]), "+f"(c[3])
        : "r"(a[0]), "r"(a[1]), "r"(a[2]), "r"(a[3]), "r"(b0), "r"(b1));
}

// ---------------------------------------------------------------------------
// Prepass: fp32 -> tf32(rna) + permute into fragment order.
// ---------------------------------------------------------------------------
__global__ __launch_bounds__(256) void permA(const float* __restrict__ in,
                                             float* __restrict__ out) {
    int gid = blockIdx.x * 256 + threadIdx.x;
    int lane = gid & 31, frag = gid >> 5;
    int kf = frag & 127, mf = frag >> 7;
    int mi = lane >> 2, ki = lane & 3;
    const float* p = in + (size_t)(mf * 16 + mi) * CD + kf * 8 + ki;
    float4 v;
    v.x = rna_tf32(p[0]);
    v.y = rna_tf32(p[8 * CD]);
    v.z = rna_tf32(p[4]);
    v.w = rna_tf32(p[8 * CD + 4]);
    ((float4*)out)[gid] = v;
}
// All 4 weights in one launch: blockIdx.y selects the weight.
__global__ __launch_bounds__(256) void permW(const float* __restrict__ w0,
                                             const float* __restrict__ w1,
                                             const float* __restrict__ w2,
                                             const float* __restrict__ w3,
                                             float* __restrict__ out) {
    int wsel = blockIdx.y;
    const float* in = (wsel == 0) ? w0 : (wsel == 1) ? w1 : (wsel == 2) ? w2 : w3;
    float* dst = out + (size_t)wsel * CD * CD;
    int gid = blockIdx.x * 256 + threadIdx.x;
    int lane = gid & 31, frag = gid >> 5;
    int kf = frag & 127, nf = frag >> 7;
    int ni = lane >> 2, ki = lane & 3;
    const float* p = in + (size_t)(nf * 8 + ni) * CD + kf * 8 + ki;
    ((float2*)dst)[gid] = make_float2(rna_tf32(p[0]), rna_tf32(p[4]));
}

// ---------------------------------------------------------------------------
// tf32 GEMM on pre-permuted fragments (R8 tiling: BN=128, NSTG=3, warp tile
// 64x32). Single-sync pipelined mainloop: prologue fills 2 stages; each
// iteration waits, syncs (freeing stage kt-1), issues into it, then mmas.
// mode 0: row-major fp32 out
// mode 1: Q=RoPE->Q-frags  mode 2: K=RoPE->K-frags  mode 3: V->V-frags
// ---------------------------------------------------------------------------
__global__ __launch_bounds__(256) void gemm_f(
    const float* __restrict__ A, const float* __restrict__ W,
    float* __restrict__ out, int mode)
{
    extern __shared__ float sm[];
    const uint32_t sbase = smem_u32(sm);
    const int tid = threadIdx.x;
    const int wid = tid >> 5, lane = tid & 31;
    const int wr = wid >> 2, wc = wid & 3;      // 2 x 4 warp grid
    const int m0 = blockIdx.y * BM, n0 = blockIdx.x * BN;

    auto issue = [&](int kt) {
        int st = kt % NSTG;
        uint32_t dA = sbase + st * STG_B;
        #pragma unroll
        for (int p = 0; p < 4; p++) {           // 1024 x 16B = 16KB
            int idx = tid + p * 256;
            int fm = idx >> 7, inner = idx & 127;
            const float* s = A + ((size_t)(m0 / 16 + fm) * (CD / 8) + kt * 4) * 128 + inner * 4;
            cpasync16(dA + idx * 16, s);
        }
        uint32_t dB = dA + A_STG_B;
        #pragma unroll
        for (int p = 0; p < 4; p++) {           // 1024 x 16B = 16KB
            int idx = tid + p * 256;
            int fn = idx >> 6, inner = idx & 63;
            const float* s = W + ((size_t)(n0 / 8 + fn) * (CD / 8) + kt * 4) * 64 + inner * 4;
            cpasync16(dB + idx * 16, s);
        }
        asm volatile("cp.async.commit_group;");
    };

    issue(0);
    issue(1);

    float acc[4][4][4] = {};

    for (int kt = 0; kt < NITER; kt++) {
        const int st = kt % NSTG;
        const float* As = sm + st * (STG_B / 4);
        const float* Bs = As + (A_STG_B / 4);
        CP_WAIT(1);                 // group kt complete (one group committed/iter)
        __syncthreads();            // also frees stage (kt-1)%NSTG for rewrite
        if (kt + 2 < NITER) issue(kt + 2);
        else CP_COMMIT();           // keep group count uniform
        #pragma unroll
        for (int fk = 0; fk < 4; fk++) {
            uint32_t a[4][4], b[4][2];
            #pragma unroll
            for (int am = 0; am < 4; am++) {
                uint4 t = *(const uint4*)&As[(((wr * 4 + am) * 4 + fk) * 32 + lane) * 4];
                a[am][0] = t.x; a[am][1] = t.y; a[am][2] = t.z; a[am][3] = t.w;
            }
            #pragma unroll
            for (int bn = 0; bn < 4; bn++) {
                uint2 t = *(const uint2*)&Bs[(((wc * 4 + bn) * 4 + fk) * 32 + lane) * 2];
                b[bn][0] = t.x; b[bn][1] = t.y;
            }
            #pragma unroll
            for (int am = 0; am < 4; am++)
                #pragma unroll
                for (int bn = 0; bn < 4; bn++)
                    mma8(acc[am][bn], a[am], b[bn][0], b[bn][1]);
        }
    }

    // ---- epilogue
    const int qrow = lane >> 2, qcol = (lane & 3) * 2;
    #pragma unroll
    for (int am = 0; am < 4; am++) {
        #pragma unroll
        for (int half = 0; half < 2; half++) {
            int m = m0 + (wr * 4 + am) * 16 + qrow + half * 8;
            int b_ = m >> 11, t = m & (CT - 1);
            #pragma unroll
            for (int bn = 0; bn < 4; bn++) {
                int col = n0 + (wc * 4 + bn) * 8 + qcol;
                float v0 = acc[am][bn][half * 2 + 0];
                float v1 = acc[am][bn][half * 2 + 1];
                if (mode == 0) {
                    *(float2*)&out[(size_t)m * CD + col] = make_float2(v0, v1);
                } else {
                    int h = col >> 6, d0 = col & 63;
                    int bh = b_ * CH + h;
                    if (mode <= 2) {   // RoPE for Q and K
                        int pidx = d0 >> 1;
                        float inv = exp2f(-(float)pidx * (9.965784284662087f / 32.0f));
                        float sn, cs;
                        sincosf((float)t * inv, &sn, &cs);
                        float re = v0 * cs - v1 * sn;
                        float ro = v0 * sn + v1 * cs;
                        v0 = re; v1 = ro;
                    }
                    if (mode == 1) {           // Q A-frags per (bh,qb64)
                        int qb = t >> 6, tq = t & 63, mf = tq >> 4, mi = tq & 15;
                        int kf = d0 >> 3, ki = d0 & 7;
                        int ls = (mi & 7) * 4 + (ki & 3);
                        int slot = ((ki & 4) >> 1) | (mi >> 3);
                        float* p = out + ((size_t)((bh * 32 + qb) * 4 + mf) * 8 + kf) * 128
                                       + ls * 4 + slot;
                        p[0] = rna_tf32(v0); p[4] = rna_tf32(v1);
                    } else if (mode == 2) {    // K B-frags per (bh,kb64)
                        int kb = t >> 6, tk = t & 63, nf = tk >> 3, ni = tk & 7;
                        int kf = d0 >> 3, ki = d0 & 7;
                        int ls = ni * 4 + (ki & 3), slot = ki >> 2;
                        float* p = out + ((size_t)((bh * 32 + kb) * 8 + kf) * 8 + nf) * 64
                                       + ls * 2 + slot;
                        p[0] = rna_tf32(v0); p[2] = rna_tf32(v1);
                    } else {                   // V B-frags per (bh,kb64)
                        int kb = t >> 6, keyl = t & 63, kf = keyl >> 3, ki = keyl & 7;
                        int nf = d0 >> 3, ni = d0 & 7;
                        int ls = ni * 4 + (ki & 3), slot = ki >> 2;
                        float* p = out + ((size_t)((bh * 32 + kb) * 8 + kf) * 8 + nf) * 64
                                       + ls * 2 + slot;
                        p[0] = rna_tf32(v0); p[8] = rna_tf32(v1);
                    }
                }
            }
        }
    }
}

// ---------------------------------------------------------------------------
// Flash attention (R8 tiling: Br=64, 128 threads), single-sync loop:
// wait -> sync (frees the other KV stage) -> prefetch next tile -> compute.
// Q A-frags gmem->regs directly; softmax on accumulator layout; P -> A-frag
// via register shuffles. cat written as A-frags.
// ---------------------------------------------------------------------------
__global__ __launch_bounds__(128) void attn_f(
    const float* __restrict__ Qp, const float* __restrict__ Kp,
    const float* __restrict__ Vp, float* __restrict__ catp)
{
    extern __shared__ float sm[];
    const uint32_t sbase = smem_u32(sm);
    const int qb = blockIdx.x, bh = blockIdx.y;
    const int tid = threadIdx.x, wid = tid >> 5, lane = tid & 31;

    // Q A-frags straight to registers (warp wid owns mf=wid), scaled by 1/8
    uint32_t qa[8][4];
    {
        const float* qsrc = Qp + ((size_t)((bh * 32 + qb) * 4 + wid)) * 1024 + lane * 4;
        #pragma unroll
        for (int kf = 0; kf < 8; kf++) {
            float4 t = *(const float4*)(qsrc + kf * 128);
            qa[kf][0] = __float_as_uint(t.x * 0.125f);
            qa[kf][1] = __float_as_uint(t.y * 0.125f);
            qa[kf][2] = __float_as_uint(t.z * 0.125f);
            qa[kf][3] = __float_as_uint(t.w * 0.125f);
        }
    }

    auto issueKV = [&](int kb) {
        int st = kb & 1;
        uint32_t d = sbase + st * 32768;
        const float* srcK = Kp + ((size_t)(bh * 32 + kb)) * 4096;
        const float* srcV = Vp + ((size_t)(bh * 32 + kb)) * 4096;
        #pragma unroll
        for (int u = 0; u < 8; u++) {
            int idx = tid + u * 128;
            cpasync16(d + idx * 16, srcK + idx * 4);
            cpasync16(d + 16384 + idx * 16, srcV + idx * 4);
        }
    };

    issueKV(0); CP_COMMIT();

    float m_[2] = {-1e30f, -1e30f}, l_[2] = {0.0f, 0.0f};
    float O[8][4] = {};

    const int src0 = (lane & ~3) | ((lane & 3) >> 1);
    const int src2 = src0 | 2;
    const bool sel = lane & 1;
    const int row0 = wid * 16 + (lane >> 2);

    for (int kb = 0; kb <= qb; kb++) {
        CP_WAIT(0);                 // this tile's KV in smem
        __syncthreads();            // all warps done with the other stage
        if (kb < qb) issueKV(kb + 1);
        CP_COMMIT();
        const float* Ks = sm + (kb & 1) * 8192;
        const float* Vs = Ks + 4096;

        // ---- S = Q K^T
        float S[8][4] = {};
        #pragma unroll
        for (int kf = 0; kf < 8; kf++) {
            #pragma unroll
            for (int nf = 0; nf < 8; nf++) {
                uint2 kfr = *(const uint2*)&Ks[((kf * 8 + nf) * 32 + lane) * 2];
                mma8(S[nf], qa[kf], kfr.x, kfr.y);
            }
        }

        if (kb == qb) {
            #pragma unroll
            for (int nf = 0; nf < 8; nf++)
                #pragma unroll
                for (int e = 0; e < 4; e++) {
                    int col = nf * 8 + 2 * (lane & 3) + (e & 1);
                    int row = row0 + ((e >> 1) << 3);
                    if (col > row) S[nf][e] = -1e30f;
                }
        }

        // ---- online softmax (quad-lane reductions)
        #pragma unroll
        for (int h = 0; h < 2; h++) {
            float mx = -1e30f;
            #pragma unroll
            for (int nf = 0; nf < 8; nf++)
                mx = fmaxf(mx, fmaxf(S[nf][2*h], S[nf][2*h + 1]));
            mx = fmaxf(mx, __shfl_xor_sync(0xffffffffu, mx, 1));
            mx = fmaxf(mx, __shfl_xor_sync(0xffffffffu, mx, 2));
            float mn = fmaxf(m_[h], mx);
            float sc = __expf(m_[h] - mn);
            float rs = 0.0f;
            #pragma unroll
            for (int nf = 0; nf < 8; nf++) {
                float p0 = rna_tf32(__expf(S[nf][2*h]     - mn));
                float p1 = rna_tf32(__expf(S[nf][2*h + 1] - mn));
                S[nf][2*h] = p0; S[nf][2*h + 1] = p1;
                rs += p0 + p1;
            }
            rs += __shfl_xor_sync(0xffffffffu, rs, 1);
            rs += __shfl_xor_sync(0xffffffffu, rs, 2);
            l_[h] = l_[h] * sc + rs;
            m_[h] = mn;
            #pragma unroll
            for (int nf = 0; nf < 8; nf++) { O[nf][2*h] *= sc; O[nf][2*h + 1] *= sc; }
        }

        // ---- O += P V (P -> A-frag via shfl)
        #pragma unroll
        for (int j = 0; j < 8; j++) {
            float t00 = __shfl_sync(0xffffffffu, S[j][0], src0);
            float t01 = __shfl_sync(0xffffffffu, S[j][1], src0);
            float t20 = __shfl_sync(0xffffffffu, S[j][0], src2);
            float t21 = __shfl_sync(0xffffffffu, S[j][1], src2);
            float t10 = __shfl_sync(0xffffffffu, S[j][2], src0);
            float t11 = __shfl_sync(0xffffffffu, S[j][3], src0);
            float t30 = __shfl_sync(0xffffffffu, S[j][2], src2);
            float t31 = __shfl_sync(0xffffffffu, S[j][3], src2);
            uint32_t pa[4];
            pa[0] = __float_as_uint(sel ? t01 : t00);
            pa[1] = __float_as_uint(sel ? t11 : t10);
            pa[2] = __float_as_uint(sel ? t21 : t20);
            pa[3] = __float_as_uint(sel ? t31 : t30);
            #pragma unroll
            for (int nf = 0; nf < 8; nf++) {
                uint2 vf = *(const uint2*)&Vs[((j * 8 + nf) * 32 + lane) * 2];
                mma8(O[nf], pa, vf.x, vf.y);
            }
        }
    }

    // ---- epilogue: write cat as A-frags (feeds out-proj)
    const int b_ = bh >> 4, h = bh & 15;
    #pragma unroll
    for (int h2 = 0; h2 < 2; h2++) {
        int t = qb * 64 + wid * 16 + (lane >> 2) + h2 * 8;
        int m = b_ * CT + t;
        float inv = 1.0f / l_[h2];
        int mf = m >> 4, mi = m & 15;
        #pragma unroll
        for (int nf = 0; nf < 8; nf++) {
            int d = nf * 8 + 2 * (lane & 3);
            int kcol = h * 64 + d;
            int kf = kcol >> 3, ki = d & 7;
            int ls = (mi & 7) * 4 + (ki & 3);
            int slot = ((ki & 4) >> 1) | (mi >> 3);
            float* p = catp + ((size_t)(mf * (CD / 8) + kf) * 32 + ls) * 4 + slot;
            p[0] = rna_tf32(O[nf][2*h2]     * inv);
            p[4] = rna_tf32(O[nf][2*h2 + 1] * inv);
        }
    }
}

extern "C" void kernel_launch(void* const* d_in, const int* in_sizes, int n_in,
                              void* d_out, int out_size) {
    const float* x  = (const float*)d_in[0];
    const float* wq = (const float*)d_in[1];
    const float* wk = (const float*)d_in[2];
    const float* wv = (const float*)d_in[3];
    const float* wo = (const float*)d_in[4];
    float* out = (float*)d_out;

    float *xp, *wp, *qp, *kp, *vp, *catp;
    cudaGetSymbolAddress((void**)&xp,   g_xp);
    cudaGetSymbolAddress((void**)&wp,   g_wp);
    cudaGetSymbolAddress((void**)&qp,   g_qp);
    cudaGetSymbolAddress((void**)&kp,   g_kp);
    cudaGetSymbolAddress((void**)&vp,   g_vp);
    cudaGetSymbolAddress((void**)&catp, g_catp);

    cudaFuncSetAttribute(gemm_f, cudaFuncAttributeMaxDynamicSharedMemorySize, GEMM_SMEM);
    cudaFuncSetAttribute(attn_f, cudaFuncAttributeMaxDynamicSharedMemorySize, ATTN_SMEM);

    permA<<<(CM/16)*(CD/8)*32/256, 256>>>(x, xp);
    dim3 gw((CD/8)*(CD/8)*32/256, 4);   // all 4 weights, one launch
    permW<<<gw, 256>>>(wq, wk, wv, wo, wp);

    dim3 gg(CD / BN, CM / BM);   // (8, 32)
    gemm_f<<<gg, 256, GEMM_SMEM>>>(xp, wp + 0*CD*CD, qp, 1);
    gemm_f<<<gg, 256, GEMM_SMEM>>>(xp, wp + 1*CD*CD, kp, 2);
    gemm_f<<<gg, 256, GEMM_SMEM>>>(xp, wp + 2*CD*CD, vp, 3);

    dim3 ga(CT / 64, CB * CH);   // (32, 32)
    attn_f<<<ga, 128, ATTN_SMEM>>>(qp, kp, vp, catp);

    gemm_f<<<gg, 256, GEMM_SMEM>>>(catp, wp + 3*CD*CD, out, 0);
}

// round 16
// speedup vs baseline: 1.2543x; 1.0250x over previous
#include <cuda_runtime.h>
#include <math.h>
#include <stdint.h>

#define CB 2
#define CT 2048
#define CD 1024
#define CH 16
#define CM (CB*CT)   // 4096

#define BM 128
#define BN 128
#define BK 32
#define NITER (CD/BK)   // 32
#define NSTG 2
#define A_STG_B 16384
#define B_STG_B 16384
#define STG_B (A_STG_B + B_STG_B)          // 32768
#define GEMM_SMEM (NSTG*STG_B)             // 65536
#define ATTN_SMEM (2*32768)                // 65536

// Scratch (device globals; all in fragment order)
__device__ float g_xp[CM*CD];        // x as A-frags
__device__ float g_wp[4][CD*CD];     // wq,wk,wv,wo as B-frags
__device__ float g_qp[CM*CD];        // Q A-frags per (bh,qb)
__device__ float g_kp[CM*CD];        // K B-frags per (bh,kb)
__device__ float g_vp[CM*CD];        // V B-frags per (bh,kb)
__device__ float g_catp[CM*CD];      // concat as A-frags

__device__ __forceinline__ float rna_tf32(float x) {
    uint32_t r;
    asm("cvt.rna.tf32.f32 %0, %1;" : "=r"(r) : "f"(x));
    return __uint_as_float(r);
}
__device__ __forceinline__ uint32_t smem_u32(const void* p) {
    uint32_t a;
    asm("{ .reg .u64 t; cvta.to.shared.u64 t, %1; cvt.u32.u64 %0, t; }" : "=r"(a) : "l"(p));
    return a;
}
__device__ __forceinline__ void cpasync16(uint32_t dst, const void* src) {
    asm volatile("cp.async.cg.shared.global [%0], [%1], 16;" :: "r"(dst), "l"(src));
}
#define CP_COMMIT() asm volatile("cp.async.commit_group;")
#define CP_WAIT(n)  asm volatile("cp.async.wait_group %0;" :: "n"(n))

__device__ __forceinline__ void mma8(float c[4], const uint32_t a[4],
                                     uint32_t b0, uint32_t b1) {
    asm volatile(
        "mma.sync.aligned.m16n8k8.row.col.f32.tf32.tf32.f32 "
        "{%0,%1,%2,%3}, {%4,%5,%6,%7}, {%8,%9}, {%0,%1,%2,%3};"
        : "+f"(c[0]), "+f"(c[1]), "+f"(c[2]), "+f"(c[3])
        : "r"(a[0]), "r"(a[1]), "r"(a[2]), "r"(a[3]), "r"(b0), "r"(b1));
}

// ---------------------------------------------------------------------------
// Prepass: fp32 -> tf32(rna) + permute into fragment order.
// ---------------------------------------------------------------------------
__global__ __launch_bounds__(256) void permA(const float* __restrict__ in,
                                             float* __restrict__ out) {
    int gid = blockIdx.x * 256 + threadIdx.x;
    int lane = gid & 31, frag = gid >> 5;
    int kf = frag & 127, mf = frag >> 7;
    int mi = lane >> 2, ki = lane & 3;
    const float* p = in + (size_t)(mf * 16 + mi) * CD + kf * 8 + ki;
    float4 v;
    v.x = rna_tf32(p[0]);
    v.y = rna_tf32(p[8 * CD]);
    v.z = rna_tf32(p[4]);
    v.w = rna_tf32(p[8 * CD + 4]);
    ((float4*)out)[gid] = v;
}
// All 4 weights in one launch: blockIdx.y selects the weight.
__global__ __launch_bounds__(256) void permW(const float* __restrict__ w0,
                                             const float* __restrict__ w1,
                                             const float* __restrict__ w2,
                                             const float* __restrict__ w3,
                                             float* __restrict__ out) {
    int wsel = blockIdx.y;
    const float* in = (wsel == 0) ? w0 : (wsel == 1) ? w1 : (wsel == 2) ? w2 : w3;
    float* dst = out + (size_t)wsel * CD * CD;
    int gid = blockIdx.x * 256 + threadIdx.x;
    int lane = gid & 31, frag = gid >> 5;
    int kf = frag & 127, nf = frag >> 7;
    int ni = lane >> 2, ki = lane & 3;
    const float* p = in + (size_t)(nf * 8 + ni) * CD + kf * 8 + ki;
    ((float2*)dst)[gid] = make_float2(rna_tf32(p[0]), rna_tf32(p[4]));
}

// ---------------------------------------------------------------------------
// Shared GEMM body (R8 tiling: BM=128, BN=128, warp tile 64x32).
// Double-buffered cp.async (NSTG=2, 64KB smem => 3 CTAs/SM), single sync.
// mode 0: row-major fp32 out
// mode 1: Q=RoPE->Q-frags  mode 2: K=RoPE->K-frags  mode 3: V->V-frags
// ---------------------------------------------------------------------------
__device__ __forceinline__ void gemm_core(
    const float* __restrict__ A, const float* __restrict__ W,
    float* __restrict__ out, int mode, float* sm)
{
    const uint32_t sbase = smem_u32(sm);
    const int tid = threadIdx.x;
    const int wid = tid >> 5, lane = tid & 31;
    const int wr = wid >> 2, wc = wid & 3;      // 2 x 4 warp grid
    const int m0 = blockIdx.y * BM, n0 = blockIdx.x * BN;

    auto issue = [&](int kt) {
        int st = kt & 1;
        uint32_t dA = sbase + st * STG_B;
        #pragma unroll
        for (int p = 0; p < 4; p++) {           // 1024 x 16B = 16KB
            int idx = tid + p * 256;
            int fm = idx >> 7, inner = idx & 127;
            const float* s = A + ((size_t)(m0 / 16 + fm) * (CD / 8) + kt * 4) * 128 + inner * 4;
            cpasync16(dA + idx * 16, s);
        }
        uint32_t dB = dA + A_STG_B;
        #pragma unroll
        for (int p = 0; p < 4; p++) {           // 1024 x 16B = 16KB
            int idx = tid + p * 256;
            int fn = idx >> 6, inner = idx & 63;
            const float* s = W + ((size_t)(n0 / 8 + fn) * (CD / 8) + kt * 4) * 64 + inner * 4;
            cpasync16(dB + idx * 16, s);
        }
        asm volatile("cp.async.commit_group;");
    };

    issue(0);

    float acc[4][4][4] = {};

    for (int kt = 0; kt < NITER; kt++) {
        const float* As = sm + (kt & 1) * (STG_B / 4);
        const float* Bs = As + (A_STG_B / 4);
        CP_WAIT(0);                 // tile kt resident
        __syncthreads();            // all warps past the other stage
        if (kt + 1 < NITER) issue(kt + 1);
        #pragma unroll
        for (int fk = 0; fk < 4; fk++) {
            uint32_t a[4][4], b[4][2];
            #pragma unroll
            for (int am = 0; am < 4; am++) {
                uint4 t = *(const uint4*)&As[(((wr * 4 + am) * 4 + fk) * 32 + lane) * 4];
                a[am][0] = t.x; a[am][1] = t.y; a[am][2] = t.z; a[am][3] = t.w;
            }
            #pragma unroll
            for (int bn = 0; bn < 4; bn++) {
                uint2 t = *(const uint2*)&Bs[(((wc * 4 + bn) * 4 + fk) * 32 + lane) * 2];
                b[bn][0] = t.x; b[bn][1] = t.y;
            }
            #pragma unroll
            for (int am = 0; am < 4; am++)
                #pragma unroll
                for (int bn = 0; bn < 4; bn++)
                    mma8(acc[am][bn], a[am], b[bn][0], b[bn][1]);
        }
    }

    // ---- epilogue
    const int qrow = lane >> 2, qcol = (lane & 3) * 2;
    #pragma unroll
    for (int am = 0; am < 4; am++) {
        #pragma unroll
        for (int half = 0; half < 2; half++) {
            int m = m0 + (wr * 4 + am) * 16 + qrow + half * 8;
            int b_ = m >> 11, t = m & (CT - 1);
            #pragma unroll
            for (int bn = 0; bn < 4; bn++) {
                int col = n0 + (wc * 4 + bn) * 8 + qcol;
                float v0 = acc[am][bn][half * 2 + 0];
                float v1 = acc[am][bn][half * 2 + 1];
                if (mode == 0) {
                    *(float2*)&out[(size_t)m * CD + col] = make_float2(v0, v1);
                } else {
                    int h = col >> 6, d0 = col & 63;
                    int bh = b_ * CH + h;
                    if (mode <= 2) {   // RoPE for Q and K
                        int pidx = d0 >> 1;
                        float inv = exp2f(-(float)pidx * (9.965784284662087f / 32.0f));
                        float sn, cs;
                        sincosf((float)t * inv, &sn, &cs);
                        float re = v0 * cs - v1 * sn;
                        float ro = v0 * sn + v1 * cs;
                        v0 = re; v1 = ro;
                    }
                    if (mode == 1) {           // Q A-frags per (bh,qb64)
                        int qb = t >> 6, tq = t & 63, mf = tq >> 4, mi = tq & 15;
                        int kf = d0 >> 3, ki = d0 & 7;
                        int ls = (mi & 7) * 4 + (ki & 3);
                        int slot = ((ki & 4) >> 1) | (mi >> 3);
                        float* p = out + ((size_t)((bh * 32 + qb) * 4 + mf) * 8 + kf) * 128
                                       + ls * 4 + slot;
                        p[0] = rna_tf32(v0); p[4] = rna_tf32(v1);
                    } else if (mode == 2) {    // K B-frags per (bh,kb64)
                        int kb = t >> 6, tk = t & 63, nf = tk >> 3, ni = tk & 7;
                        int kf = d0 >> 3, ki = d0 & 7;
                        int ls = ni * 4 + (ki & 3), slot = ki >> 2;
                        float* p = out + ((size_t)((bh * 32 + kb) * 8 + kf) * 8 + nf) * 64
                                       + ls * 2 + slot;
                        p[0] = rna_tf32(v0); p[2] = rna_tf32(v1);
                    } else {                   // V B-frags per (bh,kb64)
                        int kb = t >> 6, keyl = t & 63, kf = keyl >> 3, ki = keyl & 7;
                        int nf = d0 >> 3, ni = d0 & 7;
                        int ls = ni * 4 + (ki & 3), slot = ki >> 2;
                        float* p = out + ((size_t)((bh * 32 + kb) * 8 + kf) * 8 + nf) * 64
                                       + ls * 2 + slot;
                        p[0] = rna_tf32(v0); p[8] = rna_tf32(v1);
                    }
                }
            }
        }
    }
}

// Fused Q/K/V projection: blockIdx.z selects weight/output/mode. 768 blocks
// at 64KB smem => 3 CTAs/SM resident, ~37% occupancy.
__global__ __launch_bounds__(256) void gemm_qkv(
    const float* __restrict__ A, const float* __restrict__ Wbase,
    float* __restrict__ q, float* __restrict__ k, float* __restrict__ v)
{
    extern __shared__ float sm[];
    int z = blockIdx.z;
    const float* W = Wbase + (size_t)z * CD * CD;
    float* out = (z == 0) ? q : (z == 1) ? k : v;
    gemm_core(A, W, out, z + 1, sm);
}

__global__ __launch_bounds__(256) void gemm_f(
    const float* __restrict__ A, const float* __restrict__ W,
    float* __restrict__ out, int mode)
{
    extern __shared__ float sm[];
    gemm_core(A, W, out, mode, sm);
}

// ---------------------------------------------------------------------------
// Flash attention (R15 version: Br=64, 128 threads, single-sync loop).
// ---------------------------------------------------------------------------
__global__ __launch_bounds__(128) void attn_f(
    const float* __restrict__ Qp, const float* __restrict__ Kp,
    const float* __restrict__ Vp, float* __restrict__ catp)
{
    extern __shared__ float sm[];
    const uint32_t sbase = smem_u32(sm);
    const int qb = blockIdx.x, bh = blockIdx.y;
    const int tid = threadIdx.x, wid = tid >> 5, lane = tid & 31;

    // Q A-frags straight to registers (warp wid owns mf=wid), scaled by 1/8
    uint32_t qa[8][4];
    {
        const float* qsrc = Qp + ((size_t)((bh * 32 + qb) * 4 + wid)) * 1024 + lane * 4;
        #pragma unroll
        for (int kf = 0; kf < 8; kf++) {
            float4 t = *(const float4*)(qsrc + kf * 128);
            qa[kf][0] = __float_as_uint(t.x * 0.125f);
            qa[kf][1] = __float_as_uint(t.y * 0.125f);
            qa[kf][2] = __float_as_uint(t.z * 0.125f);
            qa[kf][3] = __float_as_uint(t.w * 0.125f);
        }
    }

    auto issueKV = [&](int kb) {
        int st = kb & 1;
        uint32_t d = sbase + st * 32768;
        const float* srcK = Kp + ((size_t)(bh * 32 + kb)) * 4096;
        const float* srcV = Vp + ((size_t)(bh * 32 + kb)) * 4096;
        #pragma unroll
        for (int u = 0; u < 8; u++) {
            int idx = tid + u * 128;
            cpasync16(d + idx * 16, srcK + idx * 4);
            cpasync16(d + 16384 + idx * 16, srcV + idx * 4);
        }
    };

    issueKV(0); CP_COMMIT();

    float m_[2] = {-1e30f, -1e30f}, l_[2] = {0.0f, 0.0f};
    float O[8][4] = {};

    const int src0 = (lane & ~3) | ((lane & 3) >> 1);
    const int src2 = src0 | 2;
    const bool sel = lane & 1;
    const int row0 = wid * 16 + (lane >> 2);

    for (int kb = 0; kb <= qb; kb++) {
        CP_WAIT(0);                 // this tile's KV in smem
        __syncthreads();            // all warps done with the other stage
        if (kb < qb) issueKV(kb + 1);
        CP_COMMIT();
        const float* Ks = sm + (kb & 1) * 8192;
        const float* Vs = Ks + 4096;

        // ---- S = Q K^T
        float S[8][4] = {};
        #pragma unroll
        for (int kf = 0; kf < 8; kf++) {
            #pragma unroll
            for (int nf = 0; nf < 8; nf++) {
                uint2 kfr = *(const uint2*)&Ks[((kf * 8 + nf) * 32 + lane) * 2];
                mma8(S[nf], qa[kf], kfr.x, kfr.y);
            }
        }

        if (kb == qb) {
            #pragma unroll
            for (int nf = 0; nf < 8; nf++)
                #pragma unroll
                for (int e = 0; e < 4; e++) {
                    int col = nf * 8 + 2 * (lane & 3) + (e & 1);
                    int row = row0 + ((e >> 1) << 3);
                    if (col > row) S[nf][e] = -1e30f;
                }
        }

        // ---- online softmax (quad-lane reductions)
        #pragma unroll
        for (int h = 0; h < 2; h++) {
            float mx = -1e30f;
            #pragma unroll
            for (int nf = 0; nf < 8; nf++)
                mx = fmaxf(mx, fmaxf(S[nf][2*h], S[nf][2*h + 1]));
            mx = fmaxf(mx, __shfl_xor_sync(0xffffffffu, mx, 1));
            mx = fmaxf(mx, __shfl_xor_sync(0xffffffffu, mx, 2));
            float mn = fmaxf(m_[h], mx);
            float sc = __expf(m_[h] - mn);
            float rs = 0.0f;
            #pragma unroll
            for (int nf = 0; nf < 8; nf++) {
                float p0 = rna_tf32(__expf(S[nf][2*h]     - mn));
                float p1 = rna_tf32(__expf(S[nf][2*h + 1] - mn));
                S[nf][2*h] = p0; S[nf][2*h + 1] = p1;
                rs += p0 + p1;
            }
            rs += __shfl_xor_sync(0xffffffffu, rs, 1);
            rs += __shfl_xor_sync(0xffffffffu, rs, 2);
            l_[h] = l_[h] * sc + rs;
            m_[h] = mn;
            #pragma unroll
            for (int nf = 0; nf < 8; nf++) { O[nf][2*h] *= sc; O[nf][2*h + 1] *= sc; }
        }

        // ---- O += P V (P -> A-frag via shfl)
        #pragma unroll
        for (int j = 0; j < 8; j++) {
            float t00 = __shfl_sync(0xffffffffu, S[j][0], src0);
            float t01 = __shfl_sync(0xffffffffu, S[j][1], src0);
            float t20 = __shfl_sync(0xffffffffu, S[j][0], src2);
            float t21 = __shfl_sync(0xffffffffu, S[j][1], src2);
            float t10 = __shfl_sync(0xffffffffu, S[j][2], src0);
            float t11 = __shfl_sync(0xffffffffu, S[j][3], src0);
            float t30 = __shfl_sync(0xffffffffu, S[j][2], src2);
            float t31 = __shfl_sync(0xffffffffu, S[j][3], src2);
            uint32_t pa[4];
            pa[0] = __float_as_uint(sel ? t01 : t00);
            pa[1] = __float_as_uint(sel ? t11 : t10);
            pa[2] = __float_as_uint(sel ? t21 : t20);
            pa[3] = __float_as_uint(sel ? t31 : t30);
            #pragma unroll
            for (int nf = 0; nf < 8; nf++) {
                uint2 vf = *(const uint2*)&Vs[((j * 8 + nf) * 32 + lane) * 2];
                mma8(O[nf], pa, vf.x, vf.y);
            }
        }
    }

    // ---- epilogue: write cat as A-frags (feeds out-proj)
    const int b_ = bh >> 4, h = bh & 15;
    #pragma unroll
    for (int h2 = 0; h2 < 2; h2++) {
        int t = qb * 64 + wid * 16 + (lane >> 2) + h2 * 8;
        int m = b_ * CT + t;
        float inv = 1.0f / l_[h2];
        int mf = m >> 4, mi = m & 15;
        #pragma unroll
        for (int nf = 0; nf < 8; nf++) {
            int d = nf * 8 + 2 * (lane & 3);
            int kcol = h * 64 + d;
            int kf = kcol >> 3, ki = d & 7;
            int ls = (mi & 7) * 4 + (ki & 3);
            int slot = ((ki & 4) >> 1) | (mi >> 3);
            float* p = catp + ((size_t)(mf * (CD / 8) + kf) * 32 + ls) * 4 + slot;
            p[0] = rna_tf32(O[nf][2*h2]     * inv);
            p[4] = rna_tf32(O[nf][2*h2 + 1] * inv);
        }
    }
}

extern "C" void kernel_launch(void* const* d_in, const int* in_sizes, int n_in,
                              void* d_out, int out_size) {
    const float* x  = (const float*)d_in[0];
    const float* wq = (const float*)d_in[1];
    const float* wk = (const float*)d_in[2];
    const float* wv = (const float*)d_in[3];
    const float* wo = (const float*)d_in[4];
    float* out = (float*)d_out;

    float *xp, *wp, *qp, *kp, *vp, *catp;
    cudaGetSymbolAddress((void**)&xp,   g_xp);
    cudaGetSymbolAddress((void**)&wp,   g_wp);
    cudaGetSymbolAddress((void**)&qp,   g_qp);
    cudaGetSymbolAddress((void**)&kp,   g_kp);
    cudaGetSymbolAddress((void**)&vp,   g_vp);
    cudaGetSymbolAddress((void**)&catp, g_catp);

    cudaFuncSetAttribute(gemm_qkv, cudaFuncAttributeMaxDynamicSharedMemorySize, GEMM_SMEM);
    cudaFuncSetAttribute(gemm_f,   cudaFuncAttributeMaxDynamicSharedMemorySize, GEMM_SMEM);
    cudaFuncSetAttribute(attn_f,   cudaFuncAttributeMaxDynamicSharedMemorySize, ATTN_SMEM);

    permA<<<(CM/16)*(CD/8)*32/256, 256>>>(x, xp);
    dim3 gw((CD/8)*(CD/8)*32/256, 4);   // all 4 weights, one launch
    permW<<<gw, 256>>>(wq, wk, wv, wo, wp);

    dim3 gqkv(CD / BN, CM / BM, 3);     // (8, 32, 3) = 768 blocks
    gemm_qkv<<<gqkv, 256, GEMM_SMEM>>>(xp, wp, qp, kp, vp);

    dim3 ga(CT / 64, CB * CH);          // (32, 32)
    attn_f<<<ga, 128, ATTN_SMEM>>>(qp, kp, vp, catp);

    dim3 gg(CD / BN, CM / BM);          // (8, 32)
    gemm_f<<<gg, 256, GEMM_SMEM>>>(catp, wp + 3*CD*CD, out, 0);
}